// round 9
// baseline (speedup 1.0000x reference)
#include <cuda_runtime.h>
#include <math.h>
#include <float.h>

#define Bc 2
#define Mc 8192
#define Nc (Bc * Mc)
#define KF 16
#define KN 8
#define NB 4096
#define BCAP 64

#define QPB 64                  // queries per block
#define SPLITS 8                // slice-threads per query
#define KTH (QPB * SPLITS)      // 512 threads
#define QBLKS (Mc / QPB)        // 128 per cloud; grid = 256
#define PASS_CANDS 4096         // candidates staged per pass (64KB)

// ---- scratch (device globals; no allocation allowed) ----
__device__ int    g_knn[(size_t)Nc * KF];
__device__ double g_acc[8];
__device__ int    g_hist[Bc][NB];
__device__ int    g_pref[Bc][NB];
__device__ int    g_members[Bc][NB * BCAP];
__device__ int    g_nflag;
__device__ int    g_flagq[Nc];

// ----- compare-exchange: a=min, b=max (2 ALU ops) -----
__device__ __forceinline__ void cx(unsigned& a, unsigned& b) {
    unsigned lo = min(a, b);
    b = max(a, b);
    a = lo;
}

// Batcher odd-even mergesort for n=8 (19 CE), ascending
__device__ __forceinline__ void sort8(unsigned k[8]) {
    cx(k[0],k[1]); cx(k[2],k[3]); cx(k[4],k[5]); cx(k[6],k[7]);
    cx(k[0],k[2]); cx(k[1],k[3]); cx(k[4],k[6]); cx(k[5],k[7]);
    cx(k[1],k[2]); cx(k[5],k[6]);
    cx(k[0],k[4]); cx(k[1],k[5]); cx(k[2],k[6]); cx(k[3],k[7]);
    cx(k[2],k[4]); cx(k[3],k[5]);
    cx(k[1],k[2]); cx(k[3],k[4]); cx(k[5],k[6]);
}

// bitonic cleaner len 8 (12 CE)
__device__ __forceinline__ void clean8(unsigned k[8]) {
    cx(k[0],k[4]); cx(k[1],k[5]); cx(k[2],k[6]); cx(k[3],k[7]);
    cx(k[0],k[2]); cx(k[1],k[3]); cx(k[4],k[6]); cx(k[5],k[7]);
    cx(k[0],k[1]); cx(k[2],k[3]); cx(k[4],k[5]); cx(k[6],k[7]);
}

// ================= kNN =================
// key = (float_bits(d) & 0x7FFFF800) | local_c(11 bits);  d = |c|^2-2q.c+|q|^2
// Each of 8 slice-threads keeps its top-8; union covers global top-16 unless a
// slice holds >=9 of them (detected exactly and fixed by fallback_kernel).
extern "C" __global__ void __launch_bounds__(KTH, 2)
knn_kernel(const float* __restrict__ coords) {
    extern __shared__ unsigned char sraw[];
    float4* sh = (float4*)sraw;

    const int tid = threadIdx.x;
    const int cloud = blockIdx.x >> 7;
    const int qblk = blockIdx.x & 127;
    const int qLocal = tid & (QPB - 1);
    const int split = tid >> 6;            // warp-uniform (64 threads per split)

    const float* cb = coords + (size_t)cloud * Mc * 3;
    const int q = qblk * QPB + qLocal;

    const float qx = cb[3 * q], qy = cb[3 * q + 1], qz = cb[3 * q + 2];
    const float qw = fmaf(qx, qx, fmaf(qy, qy, qz * qz));
    const float ax = -2.0f * qx, ay = -2.0f * qy, az = -2.0f * qz;

    unsigned tk[8];
#pragma unroll
    for (int t = 0; t < 8; ++t) tk[t] = 0xFFFFFFFFu;

#pragma unroll 1
    for (int pass = 0; pass < 2; ++pass) {
        __syncthreads();                         // previous consumers done
        const int wbase = pass * PASS_CANDS;
        for (int i = tid; i < PASS_CANDS; i += KTH) {
            const int jg = wbase + i;
            float x = cb[3 * jg], y = cb[3 * jg + 1], z = cb[3 * jg + 2];
            sh[i] = make_float4(x, y, z, fmaf(x, x, fmaf(y, y, z * z)));
        }
        __syncthreads();

        const float4* ps = sh + (split << 9);    // this thread's 512-slice
        const int cbase = pass << 9;             // local c base (slice-local)
#pragma unroll 2
        for (int b = 0; b < 512 / 8; ++b) {
            unsigned bk[8];
            const float4* p = ps + b * 8;
#pragma unroll
            for (int i = 0; i < 8; ++i) {
                float4 c = p[i];
                float d = fmaf(ax, c.x, fmaf(ay, c.y, fmaf(az, c.z, c.w + qw)));
                bk[i] = (__float_as_uint(d) & 0x7FFFF800u)
                      | (unsigned)(cbase + b * 8 + i);
            }
            sort8(bk);
#pragma unroll
            for (int i = 0; i < 8; ++i) tk[i] = min(tk[i], bk[7 - i]);
            clean8(tk);
        }
    }

    // ---- exact merge of 8 sorted-8 lists on (d21, global idx) ----
    __syncthreads();
    int2* bufA = (int2*)sraw;                    // [QPB][68]: 8 segs x 8 (+pad)
    int2* bufB = bufA + QPB * 68;                // [QPB][68]: 4 segs x 16 (+pad)
    int2* sm8  = bufB + QPB * 68;                // [QPB][8]: per-slice 8th key

    const int rowA = qLocal * 68 + split * 8;
#pragma unroll
    for (int t = 0; t < 8; ++t) {
        unsigned key = tk[t];
        int c = (int)(key & 0x7FFu);
        int g = ((c >> 9) << 12) + (split << 9) + (c & 511);
        bufA[rowA + t] = make_int2((int)(key >> 11), g);
    }
    sm8[qLocal * 8 + split] = make_int2((int)(tk[7] >> 11),
                                        ((int)(tk[7] & 0x7FFu) >> 9 << 12)
                                        + (split << 9) + (int)(tk[7] & 0x1FFu));
    __syncthreads();

#define MRG(SRC_A, SRC_B, LEN, DSTSTMT)                                       \
    {                                                                         \
        int ii = 0, jj = 0;                                                   \
        _Pragma("unroll 1")                                                   \
        for (int r = 0; r < 16; ++r) {                                        \
            int2 a = (SRC_A)[min(ii, (LEN) - 1)];                             \
            int2 b = (SRC_B)[min(jj, (LEN) - 1)];                             \
            bool takeA = (jj >= (LEN)) ||                                     \
                ((ii < (LEN)) && (a.x < b.x || (a.x == b.x && a.y < b.y)));   \
            int2 o = takeA ? a : b;                                           \
            ii += takeA; jj += !takeA;                                        \
            DSTSTMT;                                                          \
        }                                                                     \
    }

    if (split < 4) {   // round 1: pairs of sorted-8 -> full sorted-16
        const int2* sa = bufA + qLocal * 68 + split * 16;
        int2* dst = bufB + qLocal * 68 + split * 16;
        MRG(sa, sa + 8, 8, dst[r] = o);
    }
    __syncthreads();
    if (split < 2) {   // round 2: two sorted-16 -> smallest 16
        const int2* sa = bufB + qLocal * 68 + split * 32;
        int2* dst = bufA + qLocal * 68 + split * 16;
        MRG(sa, sa + 16, 16, dst[r] = o);
    }
    __syncthreads();
    if (split == 0) {  // round 3: final 16, write + flag check
        const int goff = cloud * Mc;
        int* out = g_knn + ((size_t)goff + q) * KF;
        const int2* sa = bufA + qLocal * 68;
        int2 last;
        MRG(sa, sa + 16, 16, { out[r] = goff + o.y; last = o; });
        // flag if any slice's kept-max could be inside the final top-16
        bool flag = false;
#pragma unroll
        for (int s = 0; s < 8; ++s) {
            int2 m = sm8[qLocal * 8 + s];
            flag |= (m.x < last.x) || (m.x == last.x && m.y <= last.y);
        }
        if (flag) {
            int slot = atomicAdd(&g_nflag, 1);
            g_flagq[slot] = goff + q;
        }
    }
}

// ================= exact fallback for flagged queries =================
__device__ __forceinline__ void ins16f(float v, int vi, float dd[16], int ii[16]) {
#pragma unroll
    for (int t = 0; t < 16; ++t) {
        bool lt = (v < dd[t]);
        float tv = lt ? dd[t] : v;
        int   ti = lt ? ii[t] : vi;
        dd[t] = lt ? v : dd[t];
        ii[t] = lt ? vi : ii[t];
        v = tv; vi = ti;
    }
}

#define FB_BLOCKS 32
#define FB_WARPS 8
__global__ void __launch_bounds__(FB_WARPS * 32)
fallback_kernel(const float* __restrict__ coords) {
    __shared__ int2 L[FB_WARPS][32][16];   // 32KB
    const int w = threadIdx.x >> 5;
    const int lane = threadIdx.x & 31;
    const int nf = g_nflag;

    for (int f = blockIdx.x * FB_WARPS + w; f < nf; f += FB_BLOCKS * FB_WARPS) {
        const int gq = g_flagq[f];
        const int cloud = gq >> 13;
        const int q = gq & (Mc - 1);
        const float* cb = coords + (size_t)cloud * Mc * 3;
        const float qx = cb[3 * q], qy = cb[3 * q + 1], qz = cb[3 * q + 2];

        float dd[16]; int ii[16];
#pragma unroll
        for (int t = 0; t < 16; ++t) { dd[t] = FLT_MAX; ii[t] = 0x7fffffff; }

        const int jb = lane * 256;
#pragma unroll 4
        for (int j = jb; j < jb + 256; ++j) {
            float dx = qx - cb[3 * j];
            float dy = qy - cb[3 * j + 1];
            float dz = qz - cb[3 * j + 2];
            float d = fmaf(dz, dz, fmaf(dy, dy, dx * dx));
            if (d < dd[15]) ins16f(d, j, dd, ii);   // ascending j: ties keep earlier
        }
#pragma unroll
        for (int t = 0; t < 16; ++t)
            L[w][lane][t] = make_int2(__float_as_int(dd[t]), ii[t]);
        __syncwarp();

        for (int s = 1; s < 32; s <<= 1) {
            if ((lane & (2 * s - 1)) == 0) {
                int2 tmp[16];
                const int2* A = L[w][lane];
                const int2* B = L[w][lane + s];
                int ia = 0, ib = 0;
#pragma unroll 1
                for (int r = 0; r < 16; ++r) {
                    int2 a = A[min(ia, 15)];
                    int2 b = B[min(ib, 15)];
                    bool takeA = (ib >= 16) ||
                        ((ia < 16) && (a.x < b.x || (a.x == b.x && a.y < b.y)));
                    tmp[r] = takeA ? a : b;
                    ia += takeA; ib += !takeA;
                }
#pragma unroll
                for (int r = 0; r < 16; ++r) L[w][lane][r] = tmp[r];
            }
            __syncwarp();
        }
        if (lane == 0) {
            int* out = g_knn + (size_t)gq * KF;
            const int goff = cloud << 13;
#pragma unroll
            for (int t = 0; t < 16; ++t) out[t] = goff + L[w][0][t].y;
        }
        __syncwarp();
    }
}

// ================= rank bucketing (exact, replaces sort) =================
__global__ void zero_kernel() {
    const int t = blockIdx.x * blockDim.x + threadIdx.x;
    if (t < 8) g_acc[t] = 0.0;
    if (t == 8) g_nflag = 0;
    for (int i = t; i < Bc * NB; i += gridDim.x * blockDim.x)
        ((int*)g_hist)[i] = 0;
}

__global__ void rank_build_kernel(const float* __restrict__ scores) {
    const int i = blockIdx.x * blockDim.x + threadIdx.x;
    if (i >= Nc) return;
    const int cloud = i >> 13;
    const int local = i & (Mc - 1);
    const float s = scores[i];
    int b = (int)(s * (float)NB);
    b = b < 0 ? 0 : (b > NB - 1 ? NB - 1 : b);
    const int slot = atomicAdd(&g_hist[cloud][b], 1);
    if (slot < BCAP) g_members[cloud][b * BCAP + slot] = local;
}

__global__ void prefix_kernel() {
    __shared__ int sc[1024];
    const int cloud = blockIdx.x;
    const int t = threadIdx.x;
    const int base = t * 4;
    int h0 = g_hist[cloud][base + 0];
    int h1 = g_hist[cloud][base + 1];
    int h2 = g_hist[cloud][base + 2];
    int h3 = g_hist[cloud][base + 3];
    int sum = h0 + h1 + h2 + h3;
    sc[t] = sum;
    __syncthreads();
    for (int off = 1; off < 1024; off <<= 1) {
        int v = (t >= off) ? sc[t - off] : 0;
        __syncthreads();
        sc[t] += v;
        __syncthreads();
    }
    int excl = sc[t] - sum;
    g_pref[cloud][base + 0] = excl; excl += h0;
    g_pref[cloud][base + 1] = excl; excl += h1;
    g_pref[cloud][base + 2] = excl; excl += h2;
    g_pref[cloud][base + 3] = excl;
}

// ================= per-point losses (+ rank dist loss) =================
__global__ void loss_points_kernel(const float* __restrict__ scores,
                                   const float* __restrict__ coords) {
    const int i = blockIdx.x * blockDim.x + threadIdx.x;
    double acc[6] = {0, 0, 0, 0, 0, 0};

    {
        const float si = scores[i];
        const float xi = coords[3 * i], yi = coords[3 * i + 1], zi = coords[3 * i + 2];
        float nsum = 0.0f;
        const int* nb = g_knn + (size_t)i * KF;
#pragma unroll
        for (int r = 0; r < KF; ++r) {
            const int n = nb[r];
            const float sn = scores[n];
            const float sd = fabsf(si - sn);
            const float x = (1.0f - sd) * 2.0f;
            const float sig = 1.0f / (1.0f + expf(-x));
            if (r < KN) {
                const float dx = xi - coords[3 * n];
                const float dy = yi - coords[3 * n + 1];
                const float dz = zi - coords[3 * n + 2];
                const float dist = sqrtf(dx * dx + dy * dy + dz * dz);
                const float w = expf(-dist * 10.0f);
                acc[0] += (double)(w * sd * sd);
                acc[1] += (double)w;
                acc[2] += (double)logf(sig + 1e-8f);
                nsum += sn;
            } else {
                acc[3] += (double)logf(1.0f - sig + 1e-8f);
            }
        }
        const float dm = si - nsum * 0.125f;
        acc[4] = (double)(dm * dm);

        const int cloud = i >> 13;
        const int local = i & (Mc - 1);
        int b = (int)(si * (float)NB);
        b = b < 0 ? 0 : (b > NB - 1 ? NB - 1 : b);
        int cnt = g_hist[cloud][b];
        cnt = cnt > BCAP ? BCAP : cnt;
        int r = 0;
        const int* mem = &g_members[cloud][b * BCAP];
        for (int k = 0; k < cnt; ++k) {
            const int m = mem[k];
            const float sm = scores[(cloud << 13) + m];
            r += (sm < si) || (sm == si && m < local);
        }
        const int rank = g_pref[cloud][b] + r;
        const float df = si - (float)rank * (1.0f / (float)(Mc - 1));
        acc[5] = (double)(df * df);
    }

    const int lane = threadIdx.x & 31;
    const int wid = threadIdx.x >> 5;
#pragma unroll
    for (int k = 0; k < 6; ++k)
#pragma unroll
        for (int o = 16; o; o >>= 1)
            acc[k] += __shfl_down_sync(0xffffffffu, acc[k], o);

    __shared__ double red[8][6];
    if (lane == 0)
#pragma unroll
        for (int k = 0; k < 6; ++k) red[wid][k] = acc[k];
    __syncthreads();
    if (wid == 0 && lane < 6) {
        double s = 0.0;
#pragma unroll
        for (int w = 0; w < 8; ++w) s += red[w][lane];
        atomicAdd(&g_acc[lane], s);
    }
}

// ================= finalize =================
__global__ void finalize_kernel(float* out) {
    const double l_loc = g_acc[0] / fmax(g_acc[1], 1e-8);
    const double l_pos = -g_acc[2] / (double)((size_t)Nc * KN);
    const double l_neg = -g_acc[3] / (double)((size_t)Nc * KN);
    const double l_con = l_pos + l_neg;
    const double l_smooth = g_acc[4] / (double)Nc;
    const double l_dist = g_acc[5] / (double)Nc;
    out[0] = (float)(1.0 * l_loc + 0.5 * l_con + 0.3 * l_dist + 0.2 * l_smooth);
}

extern "C" void kernel_launch(void* const* d_in, const int* in_sizes, int n_in,
                              void* d_out, int out_size) {
    const float* scores = (const float*)d_in[0];
    const float* coords = (const float*)d_in[1];
    (void)in_sizes; (void)n_in; (void)out_size;

    // smem: max(staging 64KB, merge bufs (68+68+8)*64 int2 = 72KB)
    const int KNN_SMEM = (QPB * 68 + QPB * 68 + QPB * 8) * (int)sizeof(int2);
    cudaFuncSetAttribute(knn_kernel,
                         cudaFuncAttributeMaxDynamicSharedMemorySize, KNN_SMEM);

    zero_kernel<<<16, 1024>>>();
    rank_build_kernel<<<Nc / 256, 256>>>(scores);
    prefix_kernel<<<Bc, 1024>>>();
    knn_kernel<<<Bc * QBLKS, KTH, KNN_SMEM>>>(coords);
    fallback_kernel<<<FB_BLOCKS, FB_WARPS * 32>>>(coords);
    loss_points_kernel<<<Nc / 256, 256>>>(scores, coords);
    finalize_kernel<<<1, 1>>>((float*)d_out);
}

// round 10
// speedup vs baseline: 1.6794x; 1.6794x over previous
#include <cuda_runtime.h>
#include <math.h>
#include <float.h>

#define Bc 2
#define Mc 8192
#define Nc (Bc * Mc)
#define KF 16
#define KN 8
#define NB 4096
#define BCAP 64

#define QPB 64                  // queries per block
#define SPLITS 8                // slice-threads per query
#define KTH (QPB * SPLITS)      // 512 threads
#define QBLKS (Mc / QPB)        // 128 per cloud; grid = 256
#define PASS_CANDS 4096         // candidates staged per pass (64KB)

// ---- scratch (device globals; no allocation allowed) ----
__device__ int    g_knn[(size_t)Nc * KF];
__device__ double g_acc[8];
__device__ int    g_hist[Bc][NB];
__device__ int    g_pref[Bc][NB];
__device__ int    g_members[Bc][NB * BCAP];
__device__ int    g_nflag2[2];
__device__ int    g_flagq2[Bc * Mc];

// ----- compare-exchange: a=min, b=max (2 ALU ops) -----
__device__ __forceinline__ void cx(unsigned& a, unsigned& b) {
    unsigned lo = min(a, b);
    b = max(a, b);
    a = lo;
}

// Batcher odd-even mergesort for n=8 (19 CE), ascending
__device__ __forceinline__ void sort8(unsigned k[8]) {
    cx(k[0],k[1]); cx(k[2],k[3]); cx(k[4],k[5]); cx(k[6],k[7]);
    cx(k[0],k[2]); cx(k[1],k[3]); cx(k[4],k[6]); cx(k[5],k[7]);
    cx(k[1],k[2]); cx(k[5],k[6]);
    cx(k[0],k[4]); cx(k[1],k[5]); cx(k[2],k[6]); cx(k[3],k[7]);
    cx(k[2],k[4]); cx(k[3],k[5]);
    cx(k[1],k[2]); cx(k[3],k[4]); cx(k[5],k[6]);
}

// bitonic cleaner len 8 (12 CE)
__device__ __forceinline__ void clean8(unsigned k[8]) {
    cx(k[0],k[4]); cx(k[1],k[5]); cx(k[2],k[6]); cx(k[3],k[7]);
    cx(k[0],k[2]); cx(k[1],k[3]); cx(k[4],k[6]); cx(k[5],k[7]);
    cx(k[0],k[1]); cx(k[2],k[3]); cx(k[4],k[5]); cx(k[6],k[7]);
}

// bitonic cleaner len 16 (32 CE)
__device__ __forceinline__ void clean16(unsigned k[16]) {
#pragma unroll
    for (int j = 8; j; j >>= 1)
#pragma unroll
        for (int i = 0; i < 16; ++i) {
            int l = i ^ j;
            if (l > i) cx(k[i], k[l]);
        }
}

// ================= kNN =================
// key = (float_bits(d) & 0x7FFFF800) | local_c(11 bits);  d = |c|^2-2q.c+|q|^2
// Each of 8 slice-threads keeps its top-8; union covers global top-16 unless a
// slice holds >=8 of them (detected conservatively and fixed by fallback_kernel).
extern "C" __global__ void __launch_bounds__(KTH, 2)
knn_kernel(const float* __restrict__ coords) {
    extern __shared__ unsigned char sraw[];
    float4* sh = (float4*)sraw;

    const int tid = threadIdx.x;
    const int cloud = blockIdx.x >> 7;
    const int qblk = blockIdx.x & 127;
    const int qLocal = tid & (QPB - 1);
    const int split = tid >> 6;            // warp-uniform (64 threads per split)

    const float* cb = coords + (size_t)cloud * Mc * 3;
    const int q = qblk * QPB + qLocal;

    const float qx = cb[3 * q], qy = cb[3 * q + 1], qz = cb[3 * q + 2];
    const float qw = fmaf(qx, qx, fmaf(qy, qy, qz * qz));
    const float ax = -2.0f * qx, ay = -2.0f * qy, az = -2.0f * qz;

    unsigned tk[8];
#pragma unroll
    for (int t = 0; t < 8; ++t) tk[t] = 0xFFFFFFFFu;

#pragma unroll 1
    for (int pass = 0; pass < 2; ++pass) {
        __syncthreads();                         // previous consumers done
        const int wbase = pass * PASS_CANDS;
        for (int i = tid; i < PASS_CANDS; i += KTH) {
            const int jg = wbase + i;
            float x = cb[3 * jg], y = cb[3 * jg + 1], z = cb[3 * jg + 2];
            sh[i] = make_float4(x, y, z, fmaf(x, x, fmaf(y, y, z * z)));
        }
        __syncthreads();

        const float4* ps = sh + (split << 9);    // this thread's 512-slice
        const int cbase = pass << 9;             // local c base (slice-local)
#pragma unroll 2
        for (int b = 0; b < 512 / 8; ++b) {
            unsigned bk[8];
            const float4* p = ps + b * 8;
#pragma unroll
            for (int i = 0; i < 8; ++i) {
                float4 c = p[i];
                float d = fmaf(ax, c.x, fmaf(ay, c.y, fmaf(az, c.z, c.w + qw)));
                bk[i] = (__float_as_uint(d) & 0x7FFFF800u)
                      | (unsigned)(cbase + b * 8 + i);
            }
            sort8(bk);
#pragma unroll
            for (int i = 0; i < 8; ++i) tk[i] = min(tk[i], bk[7 - i]);
            clean8(tk);
        }
    }

    // ---- exact merge of 8 sorted-8 lists on (d21, global idx) ----
    __syncthreads();
    int2* bufA = (int2*)sraw;                    // [QPB][68]: 8 segs x 8 (+pad)
    int2* bufB = bufA + QPB * 68;                // [QPB][68]: 4 segs x 16 (+pad)
    int2* sm8  = bufB + QPB * 68;                // [QPB][8]: per-slice 8th key

    const int rowA = qLocal * 68 + split * 8;
#pragma unroll
    for (int t = 0; t < 8; ++t) {
        unsigned key = tk[t];
        int c = (int)(key & 0x7FFu);
        int g = ((c >> 9) << 12) + (split << 9) + (c & 511);
        bufA[rowA + t] = make_int2((int)(key >> 11), g);
    }
    sm8[qLocal * 8 + split] = make_int2((int)(tk[7] >> 11),
                                        ((int)(tk[7] & 0x7FFu) >> 9 << 12)
                                        + (split << 9) + (int)(tk[7] & 0x1FFu));
    __syncthreads();

#define MRG(SRC_A, SRC_B, LEN, DSTSTMT)                                       \
    {                                                                         \
        int ii = 0, jj = 0;                                                   \
        _Pragma("unroll 1")                                                   \
        for (int r = 0; r < 16; ++r) {                                        \
            int2 a = (SRC_A)[min(ii, (LEN) - 1)];                             \
            int2 b = (SRC_B)[min(jj, (LEN) - 1)];                             \
            bool takeA = (jj >= (LEN)) ||                                     \
                ((ii < (LEN)) && (a.x < b.x || (a.x == b.x && a.y < b.y)));   \
            int2 o = takeA ? a : b;                                           \
            ii += takeA; jj += !takeA;                                        \
            DSTSTMT;                                                          \
        }                                                                     \
    }

    if (split < 4) {   // round 1: pairs of sorted-8 -> full sorted-16
        const int2* sa = bufA + qLocal * 68 + split * 16;
        int2* dst = bufB + qLocal * 68 + split * 16;
        MRG(sa, sa + 8, 8, dst[r] = o);
    }
    __syncthreads();
    if (split < 2) {   // round 2: two sorted-16 -> smallest 16
        const int2* sa = bufB + qLocal * 68 + split * 32;
        int2* dst = bufA + qLocal * 68 + split * 16;
        MRG(sa, sa + 16, 16, dst[r] = o);
    }
    __syncthreads();
    if (split == 0) {  // round 3: final 16, write + flag check
        const int goff = cloud * Mc;
        int* out = g_knn + ((size_t)goff + q) * KF;
        const int2* sa = bufA + qLocal * 68;
        int2 last;
        MRG(sa, sa + 16, 16, { out[r] = goff + o.y; last = o; });
        bool flag = false;
#pragma unroll
        for (int s = 0; s < 8; ++s) {
            int2 m = sm8[qLocal * 8 + s];
            flag |= (m.x < last.x) || (m.x == last.x && m.y <= last.y);
        }
        if (flag) {
            int slot = atomicAdd(&g_nflag2[cloud], 1);
            g_flagq2[cloud * Mc + slot] = q;   // cloud-local
        }
    }
}

// ============ exact branch-free fallback for flagged queries ============
// key = (float_bits(d) & 0xFFFFE000) | idx(13b); d = |q-c|^2 >= 0.
#define FB_BLOCKS_PC 148
#define FB_WARPS 8
__global__ void __launch_bounds__(FB_WARPS * 32)
fallback_kernel(const float* __restrict__ coords) {
    __shared__ unsigned S[FB_WARPS][32][17];
    const int w = threadIdx.x >> 5;
    const int lane = threadIdx.x & 31;
    const int cloud = blockIdx.x / FB_BLOCKS_PC;
    const int blk = blockIdx.x % FB_BLOCKS_PC;
    const int nf = g_nflag2[cloud];
    const float* cb = coords + (size_t)cloud * Mc * 3;
    const float4* cp = (const float4*)cb;

    for (int f = blk * FB_WARPS + w; f < nf; f += FB_BLOCKS_PC * FB_WARPS) {
        const int q = g_flagq2[cloud * Mc + f];
        const float qx = cb[3 * q], qy = cb[3 * q + 1], qz = cb[3 * q + 2];

        unsigned tk[16];
#pragma unroll
        for (int t = 0; t < 16; ++t) tk[t] = 0xFFFFFFFFu;

#pragma unroll 1
        for (int b = 0; b < 32; ++b) {
            const int j0 = lane * 256 + b * 8;
            const float4* p = cp + ((3 * j0) >> 2);   // j0 % 4 == 0 -> aligned
            float4 A = p[0], Bv = p[1], C = p[2], D = p[3], E = p[4], F = p[5];
            float xs[8] = {A.x, A.w, Bv.z, C.y, D.x, D.w, E.z, F.y};
            float ys[8] = {A.y, Bv.x, Bv.w, C.z, D.y, E.x, E.w, F.z};
            float zs[8] = {A.z, Bv.y, C.x, C.w, D.z, E.y, F.x, F.w};
            unsigned bk[8];
#pragma unroll
            for (int i = 0; i < 8; ++i) {
                float dx = xs[i] - qx, dy = ys[i] - qy, dz = zs[i] - qz;
                float d = fmaf(dz, dz, fmaf(dy, dy, dx * dx));
                bk[i] = (__float_as_uint(d) & 0xFFFFE000u) | (unsigned)(j0 + i);
            }
            sort8(bk);
#pragma unroll
            for (int i = 0; i < 8; ++i) tk[15 - i] = min(tk[15 - i], bk[i]);
            clean16(tk);
        }

        // cross-lane tree merge on packed keys (lexicographic == integer order)
#pragma unroll
        for (int t = 0; t < 16; ++t) S[w][lane][t] = tk[t];
        __syncwarp();
#pragma unroll
        for (int s = 1; s < 32; s <<= 1) {
            if ((lane & (2 * s - 1)) == 0) {
                unsigned ok[16];
#pragma unroll
                for (int t = 0; t < 16; ++t) ok[t] = S[w][lane + s][t];
#pragma unroll
                for (int t = 0; t < 16; ++t) tk[t] = min(tk[t], ok[15 - t]);
                clean16(tk);
#pragma unroll
                for (int t = 0; t < 16; ++t) S[w][lane][t] = tk[t];
            }
            __syncwarp();
        }
        if (lane == 0) {
            int* out = g_knn + ((size_t)cloud * Mc + q) * KF;
            const int goff = cloud * Mc;
#pragma unroll
            for (int t = 0; t < 16; ++t) out[t] = goff + (int)(tk[t] & 0x1FFFu);
        }
        __syncwarp();
    }
}

// ================= rank bucketing (exact, replaces sort) =================
__global__ void zero_kernel() {
    const int t = blockIdx.x * blockDim.x + threadIdx.x;
    if (t < 8) g_acc[t] = 0.0;
    if (t == 8) { g_nflag2[0] = 0; g_nflag2[1] = 0; }
    for (int i = t; i < Bc * NB; i += gridDim.x * blockDim.x)
        ((int*)g_hist)[i] = 0;
}

__global__ void rank_build_kernel(const float* __restrict__ scores) {
    const int i = blockIdx.x * blockDim.x + threadIdx.x;
    if (i >= Nc) return;
    const int cloud = i >> 13;
    const int local = i & (Mc - 1);
    const float s = scores[i];
    int b = (int)(s * (float)NB);
    b = b < 0 ? 0 : (b > NB - 1 ? NB - 1 : b);
    const int slot = atomicAdd(&g_hist[cloud][b], 1);
    if (slot < BCAP) g_members[cloud][b * BCAP + slot] = local;
}

__global__ void prefix_kernel() {
    __shared__ int sc[1024];
    const int cloud = blockIdx.x;
    const int t = threadIdx.x;
    const int base = t * 4;
    int h0 = g_hist[cloud][base + 0];
    int h1 = g_hist[cloud][base + 1];
    int h2 = g_hist[cloud][base + 2];
    int h3 = g_hist[cloud][base + 3];
    int sum = h0 + h1 + h2 + h3;
    sc[t] = sum;
    __syncthreads();
    for (int off = 1; off < 1024; off <<= 1) {
        int v = (t >= off) ? sc[t - off] : 0;
        __syncthreads();
        sc[t] += v;
        __syncthreads();
    }
    int excl = sc[t] - sum;
    g_pref[cloud][base + 0] = excl; excl += h0;
    g_pref[cloud][base + 1] = excl; excl += h1;
    g_pref[cloud][base + 2] = excl; excl += h2;
    g_pref[cloud][base + 3] = excl;
}

// ================= per-point losses (+ rank dist loss) =================
__global__ void loss_points_kernel(const float* __restrict__ scores,
                                   const float* __restrict__ coords) {
    const int i = blockIdx.x * blockDim.x + threadIdx.x;
    double acc[6] = {0, 0, 0, 0, 0, 0};

    {
        const float si = scores[i];
        const float xi = coords[3 * i], yi = coords[3 * i + 1], zi = coords[3 * i + 2];
        float nsum = 0.0f;
        const int* nb = g_knn + (size_t)i * KF;
#pragma unroll
        for (int r = 0; r < KF; ++r) {
            const int n = nb[r];
            const float sn = scores[n];
            const float sd = fabsf(si - sn);
            const float x = (1.0f - sd) * 2.0f;
            const float sig = 1.0f / (1.0f + expf(-x));
            if (r < KN) {
                const float dx = xi - coords[3 * n];
                const float dy = yi - coords[3 * n + 1];
                const float dz = zi - coords[3 * n + 2];
                const float dist = sqrtf(dx * dx + dy * dy + dz * dz);
                const float w = expf(-dist * 10.0f);
                acc[0] += (double)(w * sd * sd);
                acc[1] += (double)w;
                acc[2] += (double)logf(sig + 1e-8f);
                nsum += sn;
            } else {
                acc[3] += (double)logf(1.0f - sig + 1e-8f);
            }
        }
        const float dm = si - nsum * 0.125f;
        acc[4] = (double)(dm * dm);

        const int cloud = i >> 13;
        const int local = i & (Mc - 1);
        int b = (int)(si * (float)NB);
        b = b < 0 ? 0 : (b > NB - 1 ? NB - 1 : b);
        int cnt = g_hist[cloud][b];
        cnt = cnt > BCAP ? BCAP : cnt;
        int r = 0;
        const int* mem = &g_members[cloud][b * BCAP];
        for (int k = 0; k < cnt; ++k) {
            const int m = mem[k];
            const float sm = scores[(cloud << 13) + m];
            r += (sm < si) || (sm == si && m < local);
        }
        const int rank = g_pref[cloud][b] + r;
        const float df = si - (float)rank * (1.0f / (float)(Mc - 1));
        acc[5] = (double)(df * df);
    }

    const int lane = threadIdx.x & 31;
    const int wid = threadIdx.x >> 5;
#pragma unroll
    for (int k = 0; k < 6; ++k)
#pragma unroll
        for (int o = 16; o; o >>= 1)
            acc[k] += __shfl_down_sync(0xffffffffu, acc[k], o);

    __shared__ double red[8][6];
    if (lane == 0)
#pragma unroll
        for (int k = 0; k < 6; ++k) red[wid][k] = acc[k];
    __syncthreads();
    if (wid == 0 && lane < 6) {
        double s = 0.0;
#pragma unroll
        for (int w = 0; w < 8; ++w) s += red[w][lane];
        atomicAdd(&g_acc[lane], s);
    }
}

// ================= finalize =================
__global__ void finalize_kernel(float* out) {
    const double l_loc = g_acc[0] / fmax(g_acc[1], 1e-8);
    const double l_pos = -g_acc[2] / (double)((size_t)Nc * KN);
    const double l_neg = -g_acc[3] / (double)((size_t)Nc * KN);
    const double l_con = l_pos + l_neg;
    const double l_smooth = g_acc[4] / (double)Nc;
    const double l_dist = g_acc[5] / (double)Nc;
    out[0] = (float)(1.0 * l_loc + 0.5 * l_con + 0.3 * l_dist + 0.2 * l_smooth);
}

extern "C" void kernel_launch(void* const* d_in, const int* in_sizes, int n_in,
                              void* d_out, int out_size) {
    const float* scores = (const float*)d_in[0];
    const float* coords = (const float*)d_in[1];
    (void)in_sizes; (void)n_in; (void)out_size;

    const int KNN_SMEM = (QPB * 68 + QPB * 68 + QPB * 8) * (int)sizeof(int2);
    cudaFuncSetAttribute(knn_kernel,
                         cudaFuncAttributeMaxDynamicSharedMemorySize, KNN_SMEM);

    zero_kernel<<<16, 1024>>>();
    rank_build_kernel<<<Nc / 256, 256>>>(scores);
    prefix_kernel<<<Bc, 1024>>>();
    knn_kernel<<<Bc * QBLKS, KTH, KNN_SMEM>>>(coords);
    fallback_kernel<<<Bc * FB_BLOCKS_PC, FB_WARPS * 32>>>(coords);
    loss_points_kernel<<<Nc / 256, 256>>>(scores, coords);
    finalize_kernel<<<1, 1>>>((float*)d_out);
}